// round 1
// baseline (speedup 1.0000x reference)
#include <cuda_runtime.h>
#include <math.h>

#define NN 32768
#define BB 8
#define DEG 9
#define HID 64
#define NMASK (NN - 1)

// Scratch: __device__ globals (no allocation allowed in kernel_launch).
__device__ float g_bufA[(size_t)BB * NN * HID];
__device__ float g_bufB[(size_t)BB * NN * HID];
__device__ float g_t1[(size_t)BB * NN * HID];
__device__ float g_t2[(size_t)BB * NN * HID];

// ---------------------------------------------------------------------------
// Fused stencil: T1 = L x, T2 = 2 L T1 - x  (ring stencil, offsets -4..+4)
// Block handles TR rows of one batch. Halos: x needs +-8, T1 needs +-4.
// ---------------------------------------------------------------------------
template <int C, int TR>
__global__ __launch_bounds__(256) void stencil_kernel(
    const float* __restrict__ x, const float* __restrict__ vals,
    float* __restrict__ t1, float* __restrict__ t2)
{
    __shared__ __align__(16) float Xs[(TR + 16) * C];
    __shared__ __align__(16) float T1s[(TR + 8) * C];
    __shared__ float Vs[(TR + 8) * DEG];

    const int b  = blockIdx.y;
    const int r0 = blockIdx.x * TR;
    const int t  = threadIdx.x;

    const float* xb = x + (size_t)b * NN * C;

    // load x rows [r0-8, r0+TR+8)
    for (int idx = t; idx < (TR + 16) * C; idx += 256) {
        int row = idx / C, c = idx % C;
        int g = (r0 - 8 + row + NN) & NMASK;
        Xs[idx] = xb[(size_t)g * C + c];
    }
    // load vals rows [r0-4, r0+TR+4)
    for (int idx = t; idx < (TR + 8) * DEG; idx += 256) {
        int row = idx / DEG, j = idx % DEG;
        int g = (r0 - 4 + row + NN) & NMASK;
        Vs[idx] = vals[g * DEG + j];
    }
    __syncthreads();

    // T1 for rows [r0-4, r0+TR+4)
    for (int idx = t; idx < (TR + 8) * C; idx += 256) {
        int row = idx / C, c = idx % C;
        float s = 0.f;
#pragma unroll
        for (int j = 0; j < DEG; j++) s += Vs[row * DEG + j] * Xs[(row + j) * C + c];
        T1s[idx] = s;
    }
    __syncthreads();

    float* t1b = t1 + (size_t)b * NN * C;
    float* t2b = t2 + (size_t)b * NN * C;
    for (int idx = t; idx < TR * C; idx += 256) {
        int row = idx / C, c = idx % C;
        float s = 0.f;
#pragma unroll
        for (int j = 0; j < DEG; j++) s += Vs[(row + 4) * DEG + j] * T1s[(row + j) * C + c];
        float t2v = 2.f * s - Xs[(row + 8) * C + c];
        size_t o = (size_t)(r0 + row) * C + c;
        t1b[o] = T1s[(row + 4) * C + c];
        t2b[o] = t2v;
    }
}

// ---------------------------------------------------------------------------
// Tiled fp32 GEMM: out[M, 64] = [T0 | T1 | T2] (M x 3*FIN)  @  W (3*FIN x 64) + bias (+ELU)
// TILE_M = 256 rows/block, 256 threads, 8x8 micro-tile per thread.
// A chunk stored k-major in smem (stride 264 -> conflict-free, 16B aligned).
// ---------------------------------------------------------------------------
template <int FIN, bool DO_ELU>
__global__ __launch_bounds__(256) void gemm_kernel(
    const float* __restrict__ s0, const float* __restrict__ s1, const float* __restrict__ s2,
    const float* __restrict__ W, const float* __restrict__ bias, float* __restrict__ out)
{
    constexpr int FOUT = 64;
    constexpr int CK   = (FIN >= 32) ? 32 : FIN;   // k-chunk: within one segment
    constexpr int TM   = 256;
    constexpr int AS   = TM + 8;                   // 264: 16B-aligned rows, no conflicts
    constexpr int NCH  = 3 * FIN / CK;

    __shared__ __align__(16) float As[CK * AS];
    __shared__ __align__(16) float Wc[CK * FOUT];

    const int t    = threadIdx.x;
    const int m0   = blockIdx.x * TM;
    const int row0 = (t >> 3) * 8;
    const int col0 = (t & 7) * 8;

    float acc[8][8];
#pragma unroll
    for (int r = 0; r < 8; r++)
#pragma unroll
        for (int c = 0; c < 8; c++) acc[r][c] = 0.f;

    for (int ch = 0; ch < NCH; ch++) {
        const int seg = (ch * CK) / FIN;
        const int kin = (ch * CK) % FIN;
        const float* sp = (seg == 0) ? s0 : (seg == 1) ? s1 : s2;

        __syncthreads();
        // A chunk: thread t owns row (m0+t); reads CK contiguous floats, scatters k-major.
#pragma unroll
        for (int i = 0; i < CK / 4; i++) {
            float4 v = *(const float4*)&sp[(size_t)(m0 + t) * FIN + kin + i * 4];
            As[(i * 4 + 0) * AS + t] = v.x;
            As[(i * 4 + 1) * AS + t] = v.y;
            As[(i * 4 + 2) * AS + t] = v.z;
            As[(i * 4 + 3) * AS + t] = v.w;
        }
        // W chunk (L2-resident, tiny)
        for (int idx = t; idx < CK * FOUT; idx += 256) {
            Wc[idx] = W[(size_t)(ch * CK + idx / FOUT) * FOUT + (idx % FOUT)];
        }
        __syncthreads();

#pragma unroll
        for (int kk = 0; kk < CK; kk++) {
            float4 a0 = *(const float4*)&As[kk * AS + row0];
            float4 a1 = *(const float4*)&As[kk * AS + row0 + 4];
            float4 b0 = *(const float4*)&Wc[kk * FOUT + col0];
            float4 b1 = *(const float4*)&Wc[kk * FOUT + col0 + 4];
            float a[8] = {a0.x, a0.y, a0.z, a0.w, a1.x, a1.y, a1.z, a1.w};
            float bb[8] = {b0.x, b0.y, b0.z, b0.w, b1.x, b1.y, b1.z, b1.w};
#pragma unroll
            for (int r = 0; r < 8; r++)
#pragma unroll
                for (int c = 0; c < 8; c++) acc[r][c] += a[r] * bb[c];
        }
    }

    float bv[8];
#pragma unroll
    for (int c = 0; c < 8; c++) bv[c] = bias[col0 + c];

#pragma unroll
    for (int r = 0; r < 8; r++) {
        float v[8];
#pragma unroll
        for (int c = 0; c < 8; c++) {
            float z = acc[r][c] + bv[c];
            if (DO_ELU) z = (z > 0.f) ? z : expm1f(z);
            v[c] = z;
        }
        float* op = &out[(size_t)(m0 + row0 + r) * FOUT + col0];
        *(float4*)(op)     = make_float4(v[0], v[1], v[2], v[3]);
        *(float4*)(op + 4) = make_float4(v[4], v[5], v[6], v[7]);
    }
}

// ---------------------------------------------------------------------------
// Final layer: out[m, 0..1] = [T0|T1|T2](m, :) @ W5 (192x2) + b5   (no ELU)
// ---------------------------------------------------------------------------
__global__ __launch_bounds__(256) void out_kernel(
    const float* __restrict__ s0, const float* __restrict__ s1, const float* __restrict__ s2,
    const float* __restrict__ W, const float* __restrict__ bias, float* __restrict__ out)
{
    __shared__ float Ws[192 * 2];
    const int t = threadIdx.x;
    for (int idx = t; idx < 192 * 2; idx += 256) Ws[idx] = W[idx];
    __syncthreads();

    const size_t m = (size_t)blockIdx.x * 256 + t;
    float a0 = bias[0], a1 = bias[1];
#pragma unroll
    for (int seg = 0; seg < 3; seg++) {
        const float* sp = (seg == 0) ? s0 : (seg == 1) ? s1 : s2;
        const float4* p = (const float4*)(sp + m * 64);
#pragma unroll
        for (int i = 0; i < 16; i++) {
            float4 v = p[i];
            int k = (seg * 64 + i * 4) * 2;
            a0 += v.x * Ws[k + 0] + v.y * Ws[k + 2] + v.z * Ws[k + 4] + v.w * Ws[k + 6];
            a1 += v.x * Ws[k + 1] + v.y * Ws[k + 3] + v.z * Ws[k + 5] + v.w * Ws[k + 7];
        }
    }
    *(float2*)&out[m * 2] = make_float2(a0, a1);
}

// ---------------------------------------------------------------------------
extern "C" void kernel_launch(void* const* d_in, const int* in_sizes, int n_in,
                              void* d_out, int out_size)
{
    const float* x    = (const float*)d_in[0];
    const float* vals = (const float*)d_in[3];
    const float* W1 = (const float*)d_in[4];  const float* b1 = (const float*)d_in[5];
    const float* W2 = (const float*)d_in[6];  const float* b2 = (const float*)d_in[7];
    const float* W3 = (const float*)d_in[8];  const float* b3 = (const float*)d_in[9];
    const float* W4 = (const float*)d_in[10]; const float* b4 = (const float*)d_in[11];
    const float* W5 = (const float*)d_in[12]; const float* b5 = (const float*)d_in[13];

    float *bufA, *bufB, *t1, *t2;
    cudaGetSymbolAddress((void**)&bufA, g_bufA);
    cudaGetSymbolAddress((void**)&bufB, g_bufB);
    cudaGetSymbolAddress((void**)&t1,   g_t1);
    cudaGetSymbolAddress((void**)&t2,   g_t2);

    const int M = BB * NN;                // 262144 rows
    dim3 gS8(NN / 256, BB);               // stencil C=8, TR=256
    dim3 gS64(NN / 64, BB);               // stencil C=64, TR=64
    const int gG = M / 256;               // 1024 GEMM blocks

    // Layer 1: Fin=8 -> 64
    stencil_kernel<8, 256><<<gS8, 256>>>(x, vals, t1, t2);
    gemm_kernel<8, true><<<gG, 256>>>(x, t1, t2, W1, b1, bufA);

    // Layer 2
    stencil_kernel<64, 64><<<gS64, 256>>>(bufA, vals, t1, t2);
    gemm_kernel<64, true><<<gG, 256>>>(bufA, t1, t2, W2, b2, bufB);

    // Layer 3
    stencil_kernel<64, 64><<<gS64, 256>>>(bufB, vals, t1, t2);
    gemm_kernel<64, true><<<gG, 256>>>(bufB, t1, t2, W3, b3, bufA);

    // Layer 4
    stencil_kernel<64, 64><<<gS64, 256>>>(bufA, vals, t1, t2);
    gemm_kernel<64, true><<<gG, 256>>>(bufA, t1, t2, W4, b4, bufB);

    // Layer 5: Fin=64 -> 2, no ELU
    stencil_kernel<64, 64><<<gS64, 256>>>(bufB, vals, t1, t2);
    out_kernel<<<gG, 256>>>(bufB, t1, t2, W5, b5, (float*)d_out);
}

// round 4
// speedup vs baseline: 1.8579x; 1.8579x over previous
#include <cuda_runtime.h>
#include <cuda_bf16.h>
#include <math.h>
#include <stdint.h>

#define NN 32768
#define BB 8
#define DEG 9
#define HID 64
#define NMASK (NN - 1)

// Scratch (no allocation allowed in kernel_launch).
__device__ float g_bufA[(size_t)BB * NN * HID];
__device__ float g_bufB[(size_t)BB * NN * HID];
__device__ float g_t1[(size_t)BB * NN * HID];
__device__ float g_t2[(size_t)BB * NN * HID];
__device__ uint4 g_wfrag[4][3072];   // per-W packed B fragments (hi0,hi1,lo0,lo1)

// ---------------------------------------------------------------------------
// Layer-1 stencil (C=8): smem version (cheap at C=8).
// ---------------------------------------------------------------------------
template <int C, int TR>
__global__ __launch_bounds__(256) void stencil_kernel(
    const float* __restrict__ x, const float* __restrict__ vals,
    float* __restrict__ t1, float* __restrict__ t2)
{
    __shared__ __align__(16) float Xs[(TR + 16) * C];
    __shared__ __align__(16) float T1s[(TR + 8) * C];
    __shared__ float Vs[(TR + 8) * DEG];

    const int b  = blockIdx.y;
    const int r0 = blockIdx.x * TR;
    const int t  = threadIdx.x;
    const float* xb = x + (size_t)b * NN * C;

    for (int idx = t; idx < (TR + 16) * C; idx += 256) {
        int row = idx / C, c = idx % C;
        int g = (r0 - 8 + row + NN) & NMASK;
        Xs[idx] = xb[(size_t)g * C + c];
    }
    for (int idx = t; idx < (TR + 8) * DEG; idx += 256) {
        int row = idx / DEG, j = idx % DEG;
        int g = (r0 - 4 + row + NN) & NMASK;
        Vs[idx] = vals[g * DEG + j];
    }
    __syncthreads();

    for (int idx = t; idx < (TR + 8) * C; idx += 256) {
        int row = idx / C, c = idx % C;
        float s = 0.f;
#pragma unroll
        for (int j = 0; j < DEG; j++) s += Vs[row * DEG + j] * Xs[(row + j) * C + c];
        T1s[idx] = s;
    }
    __syncthreads();

    float* t1b = t1 + (size_t)b * NN * C;
    float* t2b = t2 + (size_t)b * NN * C;
    for (int idx = t; idx < TR * C; idx += 256) {
        int row = idx / C, c = idx % C;
        float s = 0.f;
#pragma unroll
        for (int j = 0; j < DEG; j++) s += Vs[(row + 4) * DEG + j] * T1s[(row + j) * C + c];
        float t2v = 2.f * s - Xs[(row + 8) * C + c];
        size_t o = (size_t)(r0 + row) * C + c;
        t1b[o] = T1s[(row + 4) * C + c];
        t2b[o] = t2v;
    }
}

// ---------------------------------------------------------------------------
// C=64 stencil, register-pipeline version.
// Block: 128 rows x 64 cols, 256 threads = 4 row-groups x 64 cols.
// Thread owns column c, 32 consecutive rows; slides x/T1 rings in registers.
// vals staged in smem padded to 12 floats/row (float4-aligned broadcasts).
// ---------------------------------------------------------------------------
__device__ __forceinline__ float vdot9(const float* __restrict__ vp,
                                       const float* __restrict__ win)
{
    float4 vA = *(const float4*)vp;
    float4 vB = *(const float4*)(vp + 4);
    float  vC = vp[8];
    return vA.x * win[0] + vA.y * win[1] + vA.z * win[2] + vA.w * win[3] +
           vB.x * win[4] + vB.y * win[5] + vB.z * win[6] + vB.w * win[7] +
           vC * win[8];
}

__global__ __launch_bounds__(256) void stencil64_v2(
    const float* __restrict__ x, const float* __restrict__ vals,
    float* __restrict__ t1, float* __restrict__ t2)
{
    constexpr int VROWS = 137;            // [r0b-4, r0b+133)
    __shared__ __align__(16) float Vs[VROWS * 12];

    const int b   = blockIdx.y;
    const int t   = threadIdx.x;
    const int c   = t & 63;
    const int g   = t >> 6;               // 0..3
    const int r0b = blockIdx.x * 128;
    const int r0  = r0b + g * 32;

    // stage vals rows [r0b-4, r0b+133)
    for (int idx = t; idx < VROWS * DEG; idx += 256) {
        int row = idx / DEG, j = idx % DEG;
        int gr = (r0b - 4 + row + NN) & NMASK;
        Vs[row * 12 + j] = vals[(size_t)gr * DEG + j];
    }
    __syncthreads();

    const float* xb = x + (size_t)b * NN * 64 + c;
    float* t1b = t1 + (size_t)b * NN * 64 + c;
    float* t2b = t2 + (size_t)b * NN * 64 + c;

#define XLD(r) __ldg(xb + (size_t)(((r) + NN) & NMASK) * 64)
    // Vs row pointer for global row r:
#define VP(r) (&Vs[((r) - r0b + 4) * 12])

    float xa[17];
#pragma unroll
    for (int i = 0; i < 17; i++) xa[i] = XLD(r0 - 8 + i);

    float t1w[9];
#pragma unroll
    for (int i = 0; i < 9; i++) t1w[i] = vdot9(VP(r0 - 4 + i), &xa[i]);

    float xw[9];
#pragma unroll
    for (int i = 0; i < 9; i++) xw[i] = xa[8 + i];

#pragma unroll
    for (int i = 0; i < 32; i++) {
        const int r = r0 + i;
        float s2 = vdot9(VP(r), t1w);
        t1b[(size_t)r * 64] = t1w[4];
        t2b[(size_t)r * 64] = 2.f * s2 - xw[0];
        // advance window
        float xn = XLD(r + 9);
#pragma unroll
        for (int j = 0; j < 8; j++) xw[j] = xw[j + 1];
        xw[8] = xn;
        float nt1 = vdot9(VP(r + 5), xw);
#pragma unroll
        for (int j = 0; j < 8; j++) t1w[j] = t1w[j + 1];
        t1w[8] = nt1;
    }
#undef XLD
#undef VP
}

// ---------------------------------------------------------------------------
// Pack W[k][64] -> per-lane B fragments for mma.m16n8k16 (hi & lo bf16 split).
// Entry e = ((s*8 + j)*32 + lane): k0 = s*16 + (lane%4)*2, n = j*8 + lane/4.
// ---------------------------------------------------------------------------
__device__ __forceinline__ uint32_t pack_bf16x2(float a, float b) {
    __nv_bfloat162 h = __floats2bfloat162_rn(a, b);
    return *(uint32_t*)&h;
}
__global__ void pack_w(const float* __restrict__ W, int KREAL, int total,
                       uint4* __restrict__ dst)
{
    int e = blockIdx.x * blockDim.x + threadIdx.x;
    if (e >= total) return;
    int l = e & 31, j = (e >> 5) & 7, s = e >> 8;
    int n = j * 8 + (l >> 2);
    int k0 = s * 16 + (l & 3) * 2;
    float w[4];
#pragma unroll
    for (int i = 0; i < 4; i++) {
        int k = k0 + (i >> 1) * 8 + (i & 1);
        w[i] = (k < KREAL) ? W[(size_t)k * 64 + n] : 0.f;
    }
    float h[4], lo[4];
#pragma unroll
    for (int i = 0; i < 4; i++) {
        __nv_bfloat16 hb = __float2bfloat16_rn(w[i]);
        h[i] = __bfloat162float(hb);
        lo[i] = w[i] - h[i];
    }
    dst[e] = make_uint4(pack_bf16x2(h[0], h[1]), pack_bf16x2(h[2], h[3]),
                        pack_bf16x2(lo[0], lo[1]), pack_bf16x2(lo[2], lo[3]));
}

// ---------------------------------------------------------------------------
// Tensor-core GEMM via mma.sync (split-bf16, 3 passes):
//   out[M,64] = [T0|T1|T2](M x 3*FIN) @ W(3*FIN x 64) + bias (+ELU)
// Block: 256 thr = 8 warps x 16 rows = 128 rows. No smem: A from gmem,
// B fragments pre-packed in g_wfrag (L1/L2 resident).
// ---------------------------------------------------------------------------
__device__ __forceinline__ void mma_bf16(float* c, const uint32_t* a,
                                         uint32_t b0, uint32_t b1) {
    asm volatile(
        "mma.sync.aligned.m16n8k16.row.col.f32.bf16.bf16.f32 "
        "{%0,%1,%2,%3}, {%4,%5,%6,%7}, {%8,%9}, {%0,%1,%2,%3};"
        : "+f"(c[0]), "+f"(c[1]), "+f"(c[2]), "+f"(c[3])
        : "r"(a[0]), "r"(a[1]), "r"(a[2]), "r"(a[3]), "r"(b0), "r"(b1));
}

template <int FIN>
__device__ __forceinline__ float2 loadA(const float* __restrict__ s0,
                                        const float* __restrict__ s1,
                                        const float* __restrict__ s2,
                                        size_t row, int k) {
    if (FIN == 64) {
        const float* sp = (k < 64) ? s0 : (k < 128) ? s1 : s2;
        return *(const float2*)(sp + row * 64 + (k & 63));
    } else {
        if (k >= 24) return make_float2(0.f, 0.f);
        const float* sp = (k < 8) ? s0 : (k < 16) ? s1 : s2;
        return *(const float2*)(sp + row * 8 + (k & 7));
    }
}

__device__ __forceinline__ void cvt_hilo(float2 v, uint32_t& hi, uint32_t& lo) {
    __nv_bfloat162 h = __floats2bfloat162_rn(v.x, v.y);
    float2 hf = __bfloat1622float2(h);
    __nv_bfloat162 l = __floats2bfloat162_rn(v.x - hf.x, v.y - hf.y);
    hi = *(uint32_t*)&h;
    lo = *(uint32_t*)&l;
}

template <int FIN, bool DO_ELU>
__global__ __launch_bounds__(256) void mma_gemm(
    const float* __restrict__ s0, const float* __restrict__ s1,
    const float* __restrict__ s2, const uint4* __restrict__ wf,
    const float* __restrict__ bias, float* __restrict__ out)
{
    constexpr int KSTEPS = (FIN == 8) ? 2 : 12;
    const int t = threadIdx.x, warp = t >> 5, l = t & 31;
    const int qr = l >> 2, qc = (l & 3) * 2;
    const size_t mb = (size_t)blockIdx.x * 128 + warp * 16;

    float acc[8][4];
#pragma unroll
    for (int j = 0; j < 8; j++)
#pragma unroll
        for (int i = 0; i < 4; i++) acc[j][i] = 0.f;

#pragma unroll
    for (int s = 0; s < KSTEPS; s++) {
        const int k0 = s * 16 + qc;
        float2 v00 = loadA<FIN>(s0, s1, s2, mb + qr,     k0);
        float2 v10 = loadA<FIN>(s0, s1, s2, mb + qr + 8, k0);
        float2 v01 = loadA<FIN>(s0, s1, s2, mb + qr,     k0 + 8);
        float2 v11 = loadA<FIN>(s0, s1, s2, mb + qr + 8, k0 + 8);
        uint32_t ahi[4], alo[4];
        cvt_hilo(v00, ahi[0], alo[0]);
        cvt_hilo(v10, ahi[1], alo[1]);
        cvt_hilo(v01, ahi[2], alo[2]);
        cvt_hilo(v11, ahi[3], alo[3]);
#pragma unroll
        for (int j = 0; j < 8; j++) {
            uint4 bfr = __ldg(&wf[(s * 8 + j) * 32 + l]);
            mma_bf16(acc[j], ahi, bfr.x, bfr.y);   // hi*hi
            mma_bf16(acc[j], ahi, bfr.z, bfr.w);   // hi*lo
            mma_bf16(acc[j], alo, bfr.x, bfr.y);   // lo*hi
        }
    }

#pragma unroll
    for (int j = 0; j < 8; j++) {
        const int n = j * 8 + qc;
        float b0 = __ldg(bias + n), b1 = __ldg(bias + n + 1);
        float z[4] = {acc[j][0] + b0, acc[j][1] + b1, acc[j][2] + b0, acc[j][3] + b1};
        if (DO_ELU) {
#pragma unroll
            for (int i = 0; i < 4; i++) z[i] = (z[i] > 0.f) ? z[i] : expm1f(z[i]);
        }
        *(float2*)(out + (mb + qr) * 64 + n)     = make_float2(z[0], z[1]);
        *(float2*)(out + (mb + qr + 8) * 64 + n) = make_float2(z[2], z[3]);
    }
}

// ---------------------------------------------------------------------------
// Final layer: out[m, 0..1] = [T0|T1|T2](m,:) @ W5 (192x2) + b5 (no ELU)
// ---------------------------------------------------------------------------
__global__ __launch_bounds__(256) void out_kernel(
    const float* __restrict__ s0, const float* __restrict__ s1, const float* __restrict__ s2,
    const float* __restrict__ W, const float* __restrict__ bias, float* __restrict__ out)
{
    __shared__ float Ws[192 * 2];
    const int t = threadIdx.x;
    for (int idx = t; idx < 192 * 2; idx += 256) Ws[idx] = W[idx];
    __syncthreads();

    const size_t m = (size_t)blockIdx.x * 256 + t;
    float a0 = bias[0], a1 = bias[1];
#pragma unroll
    for (int seg = 0; seg < 3; seg++) {
        const float* sp = (seg == 0) ? s0 : (seg == 1) ? s1 : s2;
        const float4* p = (const float4*)(sp + m * 64);
#pragma unroll
        for (int i = 0; i < 16; i++) {
            float4 v = p[i];
            int k = (seg * 64 + i * 4) * 2;
            a0 += v.x * Ws[k + 0] + v.y * Ws[k + 2] + v.z * Ws[k + 4] + v.w * Ws[k + 6];
            a1 += v.x * Ws[k + 1] + v.y * Ws[k + 3] + v.z * Ws[k + 5] + v.w * Ws[k + 7];
        }
    }
    *(float2*)&out[m * 2] = make_float2(a0, a1);
}

// ---------------------------------------------------------------------------
extern "C" void kernel_launch(void* const* d_in, const int* in_sizes, int n_in,
                              void* d_out, int out_size)
{
    const float* x    = (const float*)d_in[0];
    const float* vals = (const float*)d_in[3];
    const float* W1 = (const float*)d_in[4];  const float* b1 = (const float*)d_in[5];
    const float* W2 = (const float*)d_in[6];  const float* b2 = (const float*)d_in[7];
    const float* W3 = (const float*)d_in[8];  const float* b3 = (const float*)d_in[9];
    const float* W4 = (const float*)d_in[10]; const float* b4 = (const float*)d_in[11];
    const float* W5 = (const float*)d_in[12]; const float* b5 = (const float*)d_in[13];

    float *bufA, *bufB, *t1, *t2;
    uint4* wf;
    cudaGetSymbolAddress((void**)&bufA, g_bufA);
    cudaGetSymbolAddress((void**)&bufB, g_bufB);
    cudaGetSymbolAddress((void**)&t1,   g_t1);
    cudaGetSymbolAddress((void**)&t2,   g_t2);
    cudaGetSymbolAddress((void**)&wf,   g_wfrag);

    uint4* wf1 = wf;
    uint4* wf2 = wf + 3072;
    uint4* wf3 = wf + 2 * 3072;
    uint4* wf4 = wf + 3 * 3072;

    // Pack weights into mma B-fragment layout (tiny, runs every call: deterministic)
    pack_w<<<2, 256>>>(W1, 24, 512, wf1);
    pack_w<<<12, 256>>>(W2, 192, 3072, wf2);
    pack_w<<<12, 256>>>(W3, 192, 3072, wf3);
    pack_w<<<12, 256>>>(W4, 192, 3072, wf4);

    const int M = BB * NN;                 // 262144 rows
    dim3 gS8(NN / 256, BB);                // layer-1 stencil
    dim3 gS64(NN / 128, BB);               // stencil64_v2: 128 rows/block
    const int gG = M / 128;                // 2048 GEMM blocks
    const int gO = M / 256;

    // Layer 1: Fin=8 -> 64
    stencil_kernel<8, 256><<<gS8, 256>>>(x, vals, t1, t2);
    mma_gemm<8, true><<<gG, 256>>>(x, t1, t2, wf1, b1, bufA);

    // Layer 2
    stencil64_v2<<<gS64, 256>>>(bufA, vals, t1, t2);
    mma_gemm<64, true><<<gG, 256>>>(bufA, t1, t2, wf2, b2, bufB);

    // Layer 3
    stencil64_v2<<<gS64, 256>>>(bufB, vals, t1, t2);
    mma_gemm<64, true><<<gG, 256>>>(bufB, t1, t2, wf3, b3, bufA);

    // Layer 4
    stencil64_v2<<<gS64, 256>>>(bufA, vals, t1, t2);
    mma_gemm<64, true><<<gG, 256>>>(bufA, t1, t2, wf4, b4, bufB);

    // Layer 5: Fin=64 -> 2, no ELU
    stencil64_v2<<<gS64, 256>>>(bufB, vals, t1, t2);
    out_kernel<<<gO, 256>>>(bufB, t1, t2, W5, b5, (float*)d_out);
}